// round 8
// baseline (speedup 1.0000x reference)
#include <cuda_runtime.h>

#define NROWS 2048
#define DFEAT 128
#define BLOCK 256
#define NWARP (BLOCK / 32)
#define RPB   4
#define GRID  (NROWS / RPB)

__global__ __launch_bounds__(BLOCK) void distance_sparse_kernel(
    const float* __restrict__ feats,
    const float* __restrict__ adj,
    float* __restrict__ out)
{
    const int tid  = threadIdx.x;
    const int lane = tid & 31;
    const int warp = tid >> 5;
    const int sub  = lane & 7;    // sublane within 8-lane group
    const int grp  = lane >> 3;   // group 0..3: one column per group

    __shared__ unsigned short nzidx[NROWS];  // 4 KB
    __shared__ float          evals[NROWS];  // 8 KB
    __shared__ float          wpart[NWARP];
    __shared__ int            cnt;

    const int row0 = blockIdx.x * RPB;
    const unsigned lt = (1u << lane) - 1u;

    // ---- prime the pipeline: adj row 0 loads into registers ----
    const float4* ar = reinterpret_cast<const float4*>(adj + (size_t)row0 * NROWS);
    float4 a0 = ar[tid];
    float4 a1 = ar[tid + BLOCK];

    if (tid == 0) cnt = 0;

    for (int r = 0; r < RPB; r++) {
        const int i = row0 + r;

        // ---- prefetch next row's adj while this row computes ----
        float4 n0, n1;
        if (r + 1 < RPB) {
            const float4* nr = reinterpret_cast<const float4*>(adj + (size_t)(i + 1) * NROWS);
            n0 = nr[tid];
            n1 = nr[tid + BLOCK];
        }

        // fi slices for this row (feats hot in L1/L2)
        const float4* fi4p = reinterpret_cast<const float4*>(feats + (size_t)i * DFEAT);
        float4 fi[4];
        #pragma unroll
        for (int t = 0; t < 4; t++) fi[t] = fi4p[sub + 8 * t];

        // zero-fill this row's output early (fire-and-forget; ordered before
        // the scatter by the barriers below)
        float4* orow4 = reinterpret_cast<float4*>(out + (size_t)i * NROWS);
        const float4 z = make_float4(0.f, 0.f, 0.f, 0.f);
        orow4[tid]         = z;
        orow4[tid + BLOCK] = z;

        __syncthreads();  // cnt reset visible; previous row's scatter done with nzidx/evals

        // ---- Phase 1: ballot-compact nonzero columns ----
        #pragma unroll
        for (int c = 0; c < 2; c++) {
            const float4 av = (c == 0) ? a0 : a1;
            const int t = tid + c * BLOCK;
            const unsigned b0 = __ballot_sync(0xffffffffu, av.x != 0.0f);
            const unsigned b1 = __ballot_sync(0xffffffffu, av.y != 0.0f);
            const unsigned b2 = __ballot_sync(0xffffffffu, av.z != 0.0f);
            const unsigned b3 = __ballot_sync(0xffffffffu, av.w != 0.0f);
            const int c0 = __popc(b0), c1 = __popc(b1), c2 = __popc(b2), c3 = __popc(b3);
            int base = 0;
            if (lane == 0) base = atomicAdd(&cnt, c0 + c1 + c2 + c3);
            base = __shfl_sync(0xffffffffu, base, 0);
            const int col = t * 4;
            if (av.x != 0.0f) nzidx[base + __popc(b0 & lt)]                = (unsigned short)(col);
            if (av.y != 0.0f) nzidx[base + c0 + __popc(b1 & lt)]           = (unsigned short)(col + 1);
            if (av.z != 0.0f) nzidx[base + c0 + c1 + __popc(b2 & lt)]      = (unsigned short)(col + 2);
            if (av.w != 0.0f) nzidx[base + c0 + c1 + c2 + __popc(b3 & lt)] = (unsigned short)(col + 3);
        }
        __syncthreads();
        const int m = cnt;

        // ---- Phase 2: 8-lane group per column, 4 cols/pass, 2x unrolled ----
        for (int k4 = warp; k4 * 4 < m; k4 += 2 * NWARP) {
            const int  idxA = k4 * 4 + grp;
            const int  idxB = (k4 + NWARP) * 4 + grp;
            const bool actA = idxA < m;
            const bool actB = idxB < m;
            const int  jA = actA ? (int)nzidx[idxA] : 0;
            const int  jB = actB ? (int)nzidx[idxB] : 0;
            const float4* fjA = reinterpret_cast<const float4*>(feats + (size_t)jA * DFEAT);
            const float4* fjB = reinterpret_cast<const float4*>(feats + (size_t)jB * DFEAT);

            float sA = 0.0f, sB = 0.0f;
            #pragma unroll
            for (int t = 0; t < 4; t++) {
                const float4 fa = fjA[sub + 8 * t];
                sA += (fabsf(fi[t].x - fa.x) + fabsf(fi[t].y - fa.y))
                    + (fabsf(fi[t].z - fa.z) + fabsf(fi[t].w - fa.w));
            }
            #pragma unroll
            for (int t = 0; t < 4; t++) {
                const float4 fb = fjB[sub + 8 * t];
                sB += (fabsf(fi[t].x - fb.x) + fabsf(fi[t].y - fb.y))
                    + (fabsf(fi[t].z - fb.z) + fabsf(fi[t].w - fb.w));
            }
            #pragma unroll
            for (int o = 4; o >= 1; o >>= 1) {
                sA += __shfl_xor_sync(0xffffffffu, sA, o);
                sB += __shfl_xor_sync(0xffffffffu, sB, o);
            }
            if (sub == 0) {
                if (actA) evals[idxA] = sA;
                if (actB) evals[idxB] = sB;
            }
        }
        __syncthreads();
        if (tid == 0) cnt = 0;   // reset for next row (ordered by phase-3a barriers)

        // ---- Phase 3a: batched exp + block reduction of rowsum ----
        float local = 0.0f;
        for (int t = tid; t < m; t += BLOCK) {
            const float e = __expf(-0.01f * evals[t]);
            evals[t] = e;
            local += e;
        }
        #pragma unroll
        for (int o = 16; o >= 1; o >>= 1)
            local += __shfl_xor_sync(0xffffffffu, local, o);
        if (lane == 0) wpart[warp] = local;
        __syncthreads();
        if (tid == 0) {
            float s = 0.0f;
            #pragma unroll
            for (int w = 0; w < NWARP; w++) s += wpart[w];
            wpart[0] = 1.0f / fmaxf(s, 1e-12f);
        }
        __syncthreads();

        // ---- Phase 3b: scatter normalized values ----
        const float inv = wpart[0];
        float* orow = out + (size_t)i * NROWS;
        for (int t = tid; t < m; t += BLOCK)
            orow[nzidx[t]] = evals[t] * inv;

        a0 = n0;
        a1 = n1;
    }
}

extern "C" void kernel_launch(void* const* d_in, const int* in_sizes, int n_in,
                              void* d_out, int out_size)
{
    const float* feats = (const float*)d_in[0];
    const float* adj   = (const float*)d_in[1];
    float* out         = (float*)d_out;
    distance_sparse_kernel<<<GRID, BLOCK>>>(feats, adj, out);
}